// round 3
// baseline (speedup 1.0000x reference)
#include <cuda_runtime.h>

// Problem dims (fixed by the dataset)
#define Bdim 16
#define Sdim 4096
#define Hdim 512
#define Gdim 2
#define Vdim 320
#define Ddim 128
#define GDdim 256
#define NTOK (Bdim * Sdim)           // 65536
#define TOK 32                        // tokens per CTA
#define NCTA (NTOK / TOK)             // 2048

// Output layout: concatenation of reference's return tuple, flattened:
//   quantized_features [B,S,G*D]  -> 16,777,216 floats @ 0
//   encodings          [G,B,S,V]  -> 41,943,040 floats @ 16,777,216
//   distances          [G,B,S,V]  -> 41,943,040 floats @ 58,720,256
//   perplexity         scalar     -> 1 float           @ 100,663,296
#define Q_OFF    0
#define ENC_OFF  16777216
#define DIST_OFF 58720256
#define PERP_OFF 100663296

// device scratch (allocation-free rule: __device__ globals)
__device__ double g_c2d[Gdim * Vdim];
__device__ int    g_counts[Gdim * Vdim];

// ---------------------------------------------------------------------------
// Prep: zero histogram, precompute ||c||^2 per codevector in DOUBLE (exact)
// ---------------------------------------------------------------------------
__global__ void prep_kernel(const float* __restrict__ C) {
    int i = threadIdx.x;
    if (i < Gdim * Vdim) {
        g_counts[i] = 0;
        const float* c = C + (size_t)i * Ddim;
        double s = 0.0;
#pragma unroll 8
        for (int d = 0; d < Ddim; d++) {
            double cd = (double)c[d];
            s = fma(cd, cd, s);
        }
        g_c2d[i] = s;
    }
}

// ---------------------------------------------------------------------------
// Main fused kernel: projection GEMM + distance GEMM + fp64 argmin + outputs
// smem layout (floats):
//   hs   [32][256]   @ 0      (projected h, token-major)
//   buf  [10240]     @ 8192   (W tile 32x256 stage1 / C tile 32x320 stage2)
//   Xs   [32][32]    @ 18432
//   c2d  [640 dbl]   @ 19456  (1280 float slots, 8B aligned)
//   bias [256]       @ 20736
//   h2s  [2][32]     @ 20992
// ---------------------------------------------------------------------------
#define SM_HS    0
#define SM_BUF   8192
#define SM_XS    18432
#define SM_C2D   19456
#define SM_BIAS  20736
#define SM_H2    20992
#define SM_FLOATS 21056

extern __shared__ float smem[];

__global__ __launch_bounds__(256, 2)
void main_kernel(const float* __restrict__ X,   // [B*S, 512]
                 const float* __restrict__ W,   // [512, 256]
                 const float* __restrict__ bias,// [256]
                 const float* __restrict__ C,   // [2,320,128]
                 float* __restrict__ out)
{
    float*  hs  = smem + SM_HS;
    float*  buf = smem + SM_BUF;
    float*  Xs  = smem + SM_XS;
    double* c2d = (double*)(smem + SM_C2D);
    float*  bs  = smem + SM_BIAS;
    float*  h2s = smem + SM_H2;

    const int tx   = threadIdx.x;
    const int lane = tx & 31;
    const int w    = tx >> 5;          // warp id 0..7, owns tokens 4w..4w+3
    const int t0   = blockIdx.x * TOK; // never crosses a batch boundary

    // preload exact c2 (double) and bias into smem
    c2d[tx] = g_c2d[tx];
    c2d[tx + 256] = g_c2d[tx + 256];
    if (tx < 128) c2d[tx + 512] = g_c2d[tx + 512];
    bs[tx] = bias[tx];

    // ============================ Stage 1: h = X @ W + b =====================
    float acc[4][8];
#pragma unroll
    for (int i = 0; i < 4; i++)
#pragma unroll
        for (int j = 0; j < 8; j++) acc[i][j] = 0.f;

    const int ltok = tx >> 3;          // 0..31
    const int lq   = tx & 7;           // 0..7

    for (int kc = 0; kc < Hdim; kc += 32) {
        __syncthreads();
        // X tile [32 tok][32 k]
        float4 xv = *(const float4*)(X + (size_t)(t0 + ltok) * Hdim + kc + (lq << 2));
        *(float4*)(Xs + ltok * 32 + (lq << 2)) = xv;
        // W tile [32 k][256 n]
#pragma unroll
        for (int q = 0; q < 8; q++) {
            int f = tx + (q << 8);
            int r = f >> 6, c4 = (f & 63) << 2;
            *(float4*)(buf + r * 256 + c4) =
                *(const float4*)(W + (size_t)(kc + r) * GDdim + c4);
        }
        __syncthreads();
#pragma unroll 8
        for (int k = 0; k < 32; k++) {
            float aa[4];
#pragma unroll
            for (int i = 0; i < 4; i++) aa[i] = Xs[(4 * w + i) * 32 + k];
            const float* bp = buf + k * 256 + (lane << 3);
            float4 b0 = *(const float4*)(bp);
            float4 b1 = *(const float4*)(bp + 4);
            float bb[8] = {b0.x, b0.y, b0.z, b0.w, b1.x, b1.y, b1.z, b1.w};
#pragma unroll
            for (int i = 0; i < 4; i++)
#pragma unroll
                for (int j = 0; j < 8; j++)
                    acc[i][j] = fmaf(aa[i], bb[j], acc[i][j]);
        }
    }

    // epilogue: add bias, store h to smem, reduce h2 per (token, group)
    {
        float bj[8];
#pragma unroll
        for (int j = 0; j < 8; j++) bj[j] = bs[(lane << 3) + j];
        float h2p[4];
#pragma unroll
        for (int i = 0; i < 4; i++) {
            float s = 0.f;
#pragma unroll
            for (int j = 0; j < 8; j++) {
                acc[i][j] += bj[j];
                s = fmaf(acc[i][j], acc[i][j], s);
            }
            h2p[i] = s;
            float* hp = hs + (4 * w + i) * 256 + (lane << 3);
            *(float4*)(hp)     = make_float4(acc[i][0], acc[i][1], acc[i][2], acc[i][3]);
            *(float4*)(hp + 4) = make_float4(acc[i][4], acc[i][5], acc[i][6], acc[i][7]);
        }
        // lanes 0..15 hold group-0 partials, 16..31 group-1 -> butterfly in halves
#pragma unroll
        for (int off = 8; off >= 1; off >>= 1)
#pragma unroll
            for (int i = 0; i < 4; i++)
                h2p[i] += __shfl_xor_sync(0xffffffffu, h2p[i], off);
        if (lane == 0 || lane == 16) {
#pragma unroll
            for (int i = 0; i < 4; i++)
                h2s[(lane >> 4) * 32 + 4 * w + i] = h2p[i];
        }
    }

    // ===================== Stage 2: distances + argmin per group =============
    const int bidx  = t0 >> 12;     // batch
    const int sbase = t0 & 4095;    // seq offset

    for (int g = 0; g < Gdim; g++) {
        // hc accumulators: 4 tokens x 10 codevectors
        // cv indices: A: 4*lane+j (j<4), B: 128+4*lane+j, C: 256+2*lane+j (j<2)
        float hc[4][10];
#pragma unroll
        for (int i = 0; i < 4; i++)
#pragma unroll
            for (int j = 0; j < 10; j++) hc[i][j] = 0.f;

        for (int kc = 0; kc < Ddim; kc += 32) {
            __syncthreads();
            // load C chunk transposed: buf[k][v], k in [kc,kc+32), v in [0,320)
#pragma unroll
            for (int q = 0; q < 10; q++) {
                int f = tx + (q << 8);          // 0..2559
                int v = f % 320;
                int kq = f / 320;               // 0..7
                float4 cv = *(const float4*)(C + ((size_t)g * Vdim + v) * Ddim + kc + (kq << 2));
                buf[(4 * kq + 0) * 320 + v] = cv.x;
                buf[(4 * kq + 1) * 320 + v] = cv.y;
                buf[(4 * kq + 2) * 320 + v] = cv.z;
                buf[(4 * kq + 3) * 320 + v] = cv.w;
            }
            __syncthreads();
#pragma unroll 8
            for (int k = 0; k < 32; k++) {
                float aa[4];
#pragma unroll
                for (int i = 0; i < 4; i++)
                    aa[i] = hs[(4 * w + i) * 256 + g * 128 + kc + k];
                const float* bp = buf + k * 320;
                float4 bA = *(const float4*)(bp + (lane << 2));
                float4 bB = *(const float4*)(bp + 128 + (lane << 2));
                float2 bC = *(const float2*)(bp + 256 + (lane << 1));
                float bb[10] = {bA.x, bA.y, bA.z, bA.w,
                                bB.x, bB.y, bB.z, bB.w,
                                bC.x, bC.y};
#pragma unroll
                for (int i = 0; i < 4; i++)
#pragma unroll
                    for (int j = 0; j < 10; j++)
                        hc[i][j] = fmaf(aa[i], bb[j], hc[i][j]);
            }
        }

        // per-lane candidate indices and exact c2 (double)
        int cvi[10];
#pragma unroll
        for (int j = 0; j < 4; j++)  cvi[j]     = 4 * lane + j;
#pragma unroll
        for (int j = 0; j < 4; j++)  cvi[4 + j] = 128 + 4 * lane + j;
        cvi[8] = 256 + 2 * lane;
        cvi[9] = 257 + 2 * lane;
        double c2v[10];
#pragma unroll
        for (int j = 0; j < 10; j++) c2v[j] = c2d[g * Vdim + cvi[j]];

#pragma unroll
        for (int i = 0; i < 4; i++) {
            const int tok = 4 * w + i;
            const int t   = t0 + tok;
            const int s   = sbase + tok;
            const float h2v = h2s[g * 32 + tok];
            const double h2dv = (double)h2v;

            // dd = -2*hc + c2  (double; h2 is a per-token constant, excluded
            // from the comparison key to avoid its rounding entirely)
            float dv[10];
            double mv; int mi;
#pragma unroll
            for (int j = 0; j < 10; j++) {
                double dd = fma(-2.0, (double)hc[i][j], c2v[j]);
                dv[j] = (float)(h2dv + dd);
                if (j == 0) { mv = dd; mi = cvi[0]; }
                else if (dd < mv || (dd == mv && cvi[j] < mi)) { mv = dd; mi = cvi[j]; }
            }

            const size_t rowbase = ((size_t)(g * Bdim + bidx) * Sdim + s) * (size_t)Vdim;
            float* dst = out + DIST_OFF + rowbase;
            *(float4*)(dst + (lane << 2))       = make_float4(dv[0], dv[1], dv[2], dv[3]);
            *(float4*)(dst + 128 + (lane << 2)) = make_float4(dv[4], dv[5], dv[6], dv[7]);
            *(float2*)(dst + 256 + (lane << 1)) = make_float2(dv[8], dv[9]);

            // warp butterfly argmin in double, first-index tie-break
#pragma unroll
            for (int off = 16; off >= 1; off >>= 1) {
                double ov = __shfl_xor_sync(0xffffffffu, mv, off);
                int    oi = __shfl_xor_sync(0xffffffffu, mi, off);
                if (ov < mv || (ov == mv && oi < mi)) { mv = ov; mi = oi; }
            }

            // one-hot encodings
            float* enc = out + ENC_OFF + rowbase;
            float ev[10];
#pragma unroll
            for (int j = 0; j < 10; j++) ev[j] = (cvi[j] == mi) ? 1.0f : 0.0f;
            *(float4*)(enc + (lane << 2))       = make_float4(ev[0], ev[1], ev[2], ev[3]);
            *(float4*)(enc + 128 + (lane << 2)) = make_float4(ev[4], ev[5], ev[6], ev[7]);
            *(float2*)(enc + 256 + (lane << 1)) = make_float2(ev[8], ev[9]);

            // quantized features: gather winning codevector (warp covers 128 d)
            float4 qv = *(const float4*)(C + ((size_t)g * Vdim + mi) * Ddim + (lane << 2));
            *(float4*)(out + Q_OFF + (size_t)t * GDdim + g * Ddim + (lane << 2)) = qv;

            // histogram for perplexity
            if (lane == 0) atomicAdd(&g_counts[g * Vdim + mi], 1);
        }
    }
}

// ---------------------------------------------------------------------------
// Perplexity: deterministic reduction (no float atomics)
// ---------------------------------------------------------------------------
__global__ void perp_kernel(float* __restrict__ out) {
    __shared__ float ent[Gdim * Vdim];
    __shared__ float ex[Gdim];
    int i = threadIdx.x;
    if (i < Gdim * Vdim) {
        float p = (float)g_counts[i] * (1.0f / (float)NTOK);
        p = fminf(fmaxf(p, 1e-10f), 1.0f);
        ent[i] = p * logf(p + 1e-10f);
    }
    __syncthreads();
    if (i < Gdim) {
        float s = 0.f;
        for (int v = 0; v < Vdim; v++) s += ent[i * Vdim + v];
        ex[i] = expf(-s);
    }
    __syncthreads();
    if (i == 0) out[PERP_OFF] = 0.5f * (ex[0] + ex[1]);
}

// ---------------------------------------------------------------------------
extern "C" void kernel_launch(void* const* d_in, const int* in_sizes, int n_in,
                              void* d_out, int out_size) {
    const float* X    = (const float*)d_in[0];  // hidden_states [16,4096,512]
    const float* W    = (const float*)d_in[1];  // W_proj [512,256]
    const float* bias = (const float*)d_in[2];  // b_proj [256]
    const float* C    = (const float*)d_in[3];  // codevectors [2,320,128]
    float* out = (float*)d_out;

    cudaFuncSetAttribute(main_kernel, cudaFuncAttributeMaxDynamicSharedMemorySize,
                         SM_FLOATS * sizeof(float));

    prep_kernel<<<1, Gdim * Vdim>>>(C);
    main_kernel<<<NCTA, 256, SM_FLOATS * sizeof(float)>>>(X, W, bias, C, out);
    perp_kernel<<<1, Gdim * Vdim>>>(out);
}

// round 4
// speedup vs baseline: 1.6943x; 1.6943x over previous
#include <cuda_runtime.h>

// Problem dims (fixed by the dataset)
#define Bdim 16
#define Sdim 4096
#define Hdim 512
#define Gdim 2
#define Vdim 320
#define Ddim 128
#define GDdim 256
#define NTOK (Bdim * Sdim)           // 65536
#define TOK 32                        // tokens per CTA
#define NCTA (NTOK / TOK)             // 2048

// Output layout: concatenation of reference's return tuple, flattened:
//   quantized_features [B,S,G*D]  @ 0
//   encodings          [G,B,S,V]  @ 16,777,216
//   distances          [G,B,S,V]  @ 58,720,256
//   perplexity         scalar     @ 100,663,296
#define Q_OFF    0
#define ENC_OFF  16777216
#define DIST_OFF 58720256
#define PERP_OFF 100663296

// device scratch (allocation-free rule: __device__ globals)
__device__ float  g_Wp[Hdim * GDdim];        // W in mma-fragment-paired layout
__device__ float  g_Cp[Gdim * Vdim * Ddim];  // codevectors in fragment-paired layout
__device__ double g_c2d[Gdim * Vdim];        // exact ||c||^2 (double)
__device__ int    g_counts[Gdim * Vdim];

// ---------------------------------------------------------------------------
// split-TF32 helpers: hi = top-19-bits (what HMMA reads), lo = exact residual
// ---------------------------------------------------------------------------
__device__ __forceinline__ void split2(float x, unsigned& hi, unsigned& lo) {
    unsigned xb = __float_as_uint(x);
    hi = xb & 0xFFFFE000u;
    lo = __float_as_uint(x - __uint_as_float(hi));
}

__device__ __forceinline__ void mma_tf32(float* c, const unsigned* a, const unsigned* b) {
    asm volatile(
        "mma.sync.aligned.m16n8k8.row.col.f32.tf32.tf32.f32 "
        "{%0,%1,%2,%3}, {%4,%5,%6,%7}, {%8,%9}, {%0,%1,%2,%3};\n"
        : "+f"(c[0]), "+f"(c[1]), "+f"(c[2]), "+f"(c[3])
        : "r"(a[0]), "r"(a[1]), "r"(a[2]), "r"(a[3]), "r"(b[0]), "r"(b[1]));
}

// ---------------------------------------------------------------------------
// Prep: parallel. Zero counts, exact c2 (warp per codevector), and pre-permute
// W / codevectors into mma B-fragment-paired layouts:
//   pair layout: for 8x8 (k x n) subtile, lane l holds (B[k][n], B[k+4][n])
//   with k = l%4, n = l/4, stored as float2 at offset 2*l.
// ---------------------------------------------------------------------------
__global__ void prep_kernel(const float* __restrict__ W, const float* __restrict__ C) {
    int tid = blockIdx.x * blockDim.x + threadIdx.x;  // 65536 threads
    // W_paired: [kc32=0..15][kk=0..3][s=0..31][64]
    for (int e = tid; e < Hdim * GDdim; e += 65536) {
        int k = e >> 8, n = e & 255;
        int kc32 = k >> 5, k32 = k & 31, kk = k32 >> 3, k8 = k32 & 7;
        int s = n >> 3, l = (k8 & 3) + ((n & 7) << 2), slot = k8 >> 2;
        g_Wp[((((kc32 << 2) + kk) << 5) + s) * 64 + 2 * l + slot] = W[e];
    }
    // C_paired: [g][kc=0..15][s=0..39][64]
    for (int e = tid; e < Gdim * Vdim * Ddim; e += 65536) {
        int g = e / (Vdim * Ddim);
        int rem = e - g * (Vdim * Ddim);
        int v = rem >> 7, d = rem & 127;
        int kc = d >> 3, k8 = d & 7;
        int s = v >> 3, l = (k8 & 3) + ((v & 7) << 2), slot = k8 >> 2;
        g_Cp[(((g << 4) + kc) * 40 + s) * 64 + 2 * l + slot] = C[e];
    }
    // exact c2 (double): one warp per codevector, coalesced float4 loads
    int gw = tid >> 5, lane = tid & 31;
    if (gw < Gdim * Vdim) {
        float4 cv = *(const float4*)(C + (size_t)gw * Ddim + (lane << 2));
        double s = 0.0;
        s = fma((double)cv.x, (double)cv.x, s);
        s = fma((double)cv.y, (double)cv.y, s);
        s = fma((double)cv.z, (double)cv.z, s);
        s = fma((double)cv.w, (double)cv.w, s);
#pragma unroll
        for (int off = 16; off >= 1; off >>= 1)
            s += __shfl_xor_sync(0xffffffffu, s, off);
        if (lane == 0) { g_c2d[gw] = s; g_counts[gw] = 0; }
    }
}

// ---------------------------------------------------------------------------
// smem layout (float slots)
// ---------------------------------------------------------------------------
#define SM_HSP   0       // h in A-fragment-paired layout: [g][kc][row][8] = 8192
#define SM_BUF   8192    // staging: W chunk (8192) / C chunk (5120)
#define SM_XP    16384   // X tile paired: [kk=0..3][row=0..31][8] = 1024
#define SM_BIAS  17408   // 256
#define SM_C2D   17664   // 640 doubles = 1280 slots (8B aligned: 17664*4%16==0)
#define SM_H2P   18944   // [wn=0..3][row=0..31] = 128
#define SM_AMV   19072   // 128 doubles = 256 slots (8B aligned)
#define SM_AMI   19328   // 128 ints
#define SM_FMI   19456   // 32 ints
#define SM_FLOATS 19488  // ~78KB

extern __shared__ float smem[];

__global__ __launch_bounds__(256, 2)
void main_kernel(const float* __restrict__ X,   // [B*S, 512]
                 const float* __restrict__ bias,// [256]
                 const float* __restrict__ C,   // [2,320,128]
                 float* __restrict__ out)
{
    float*  hsp  = smem + SM_HSP;
    float*  buf  = smem + SM_BUF;
    float*  Xp   = smem + SM_XP;
    float*  bs   = smem + SM_BIAS;
    double* c2d  = (double*)(smem + SM_C2D);
    float*  h2p  = smem + SM_H2P;
    double* amv  = (double*)(smem + SM_AMV);
    int*    ami  = (int*)(smem + SM_AMI);
    int*    fmi  = (int*)(smem + SM_FMI);

    const int tx   = threadIdx.x;
    const int lane = tx & 31;
    const int w    = tx >> 5;
    const int wm   = w & 1;        // m-tile (rows 16*wm..)
    const int wn   = w >> 1;       // n-column 0..3
    const int t0   = blockIdx.x * TOK;
    const int r0   = (wm << 4) + (lane >> 2);
    const int r1   = r0 + 8;
    const int lq2  = (lane & 3) << 1;

    // preload c2 (double) and bias
    ((double*)c2d)[tx]       = g_c2d[tx];
    ((double*)c2d)[tx + 256] = g_c2d[tx + 256];
    if (tx < 128) ((double*)c2d)[tx + 512] = g_c2d[tx + 512];
    bs[tx] = bias[tx];

    // ==================== Stage 1: h = X @ W + b  (split-TF32 mma) ==========
    float acc[8][4];
#pragma unroll
    for (int i = 0; i < 8; i++)
#pragma unroll
        for (int j = 0; j < 4; j++) acc[i][j] = 0.f;

    const int ltok = tx >> 3;      // 0..31
    const int lqx  = tx & 7;       // 0..7

    for (int kc32 = 0; kc32 < 16; kc32++) {
        __syncthreads();
        // X tile -> paired layout Xp[kk][row][8]
        {
            float4 xv = *(const float4*)(X + (size_t)(t0 + ltok) * Hdim + (kc32 << 5) + (lqx << 2));
            int kk = lqx >> 1, slot = lqx & 1;
            float* xp = Xp + (kk << 8) + (ltok << 3) + slot;
            xp[0] = xv.x; xp[2] = xv.y; xp[4] = xv.z; xp[6] = xv.w;
        }
        // W chunk (already fragment-paired): identity float4 copy, 32KB
        {
            const float4* src = (const float4*)(g_Wp + (kc32 << 13));
            float4* dst = (float4*)buf;
#pragma unroll
            for (int q = 0; q < 8; q++) dst[tx + (q << 8)] = src[tx + (q << 8)];
        }
        __syncthreads();
#pragma unroll
        for (int kk = 0; kk < 4; kk++) {
            float2 pa = *(float2*)&Xp[(kk << 8) + (r0 << 3) + lq2];  // a0,a2
            float2 pb = *(float2*)&Xp[(kk << 8) + (r1 << 3) + lq2];  // a1,a3
            unsigned ah[4], al[4];
            split2(pa.x, ah[0], al[0]); split2(pb.x, ah[1], al[1]);
            split2(pa.y, ah[2], al[2]); split2(pb.y, ah[3], al[3]);
#pragma unroll
            for (int s8 = 0; s8 < 8; s8++) {
                float2 pw = *(float2*)&buf[(((kk << 5) + (wn << 3) + s8) << 6) + (lane << 1)];
                unsigned bh[2], bl[2];
                split2(pw.x, bh[0], bl[0]); split2(pw.y, bh[1], bl[1]);
                mma_tf32(acc[s8], ah, bh);
                mma_tf32(acc[s8], ah, bl);
                mma_tf32(acc[s8], al, bh);
            }
        }
    }

    // stage-1 epilogue: +bias, h2 partials, store h in A-fragment-paired layout
    {
        float h2a = 0.f, h2b = 0.f;
#pragma unroll
        for (int s8 = 0; s8 < 8; s8++) {
            int s   = (wn << 3) + s8;
            int col = (s << 3) + lq2;
            float2 bb = *(float2*)&bs[col];
            float v0 = acc[s8][0] + bb.x;
            float v1 = acc[s8][1] + bb.y;
            float v2 = acc[s8][2] + bb.x;
            float v3 = acc[s8][3] + bb.y;
            h2a = fmaf(v0, v0, h2a); h2a = fmaf(v1, v1, h2a);
            h2b = fmaf(v2, v2, h2b); h2b = fmaf(v3, v3, h2b);
            int g = col >> 7, cg = col & 127;
            int kc = cg >> 3, k8 = cg & 7;
            int p0 = k8 & 3, sl0 = k8 >> 2;
            int k8b = k8 + 1, p1 = k8b & 3, sl1 = k8b >> 2;
            int base = (((g << 4) + kc) << 5);
            hsp[((base + r0) << 3) + (p0 << 1) + sl0] = v0;
            hsp[((base + r0) << 3) + (p1 << 1) + sl1] = v1;
            hsp[((base + r1) << 3) + (p0 << 1) + sl0] = v2;
            hsp[((base + r1) << 3) + (p1 << 1) + sl1] = v3;
        }
        h2a += __shfl_xor_sync(0xffffffffu, h2a, 1);
        h2a += __shfl_xor_sync(0xffffffffu, h2a, 2);
        h2b += __shfl_xor_sync(0xffffffffu, h2b, 1);
        h2b += __shfl_xor_sync(0xffffffffu, h2b, 2);
        if ((lane & 3) == 0) {
            h2p[(wn << 5) + r0] = h2a;
            h2p[(wn << 5) + r1] = h2b;
        }
    }

    // ==================== Stage 2: hc + argmin per group =====================
    const int bidx  = t0 >> 12;
    const int sbase = t0 & 4095;

    for (int g = 0; g < Gdim; g++) {
        float acc2[10][4];
#pragma unroll
        for (int i = 0; i < 10; i++)
#pragma unroll
            for (int j = 0; j < 4; j++) acc2[i][j] = 0.f;

        for (int kc2 = 0; kc2 < 8; kc2++) {
            __syncthreads();
            // stage 2 kchunks of fragment-paired C: 5120 floats
            {
                const float4* src = (const float4*)(g_Cp + ((((g << 4) + (kc2 << 1)) * 40) << 6));
                float4* dst = (float4*)buf;
#pragma unroll
                for (int q = 0; q < 5; q++) dst[tx + (q << 8)] = src[tx + (q << 8)];
            }
            __syncthreads();
#pragma unroll
            for (int kk = 0; kk < 2; kk++) {
                int kc = (kc2 << 1) + kk;
                int hb = (((g << 4) + kc) << 5);
                float2 pa = *(float2*)&hsp[((hb + r0) << 3) + lq2];
                float2 pb = *(float2*)&hsp[((hb + r1) << 3) + lq2];
                unsigned ah[4], al[4];
                split2(pa.x, ah[0], al[0]); split2(pb.x, ah[1], al[1]);
                split2(pa.y, ah[2], al[2]); split2(pb.y, ah[3], al[3]);
#pragma unroll
                for (int j = 0; j < 10; j++) {
                    int s = wn * 10 + j;
                    float2 pw = *(float2*)&buf[((kk * 40 + s) << 6) + (lane << 1)];
                    unsigned bh[2], bl[2];
                    split2(pw.x, bh[0], bl[0]); split2(pw.y, bh[1], bl[1]);
                    mma_tf32(acc2[j], ah, bh);
                    mma_tf32(acc2[j], ah, bl);
                    mma_tf32(acc2[j], al, bh);
                }
            }
        }

        // ---------------- epilogue for group g ----------------
        const double h2d0 = (double)(h2p[((2 * g) << 5) + r0] + h2p[((2 * g + 1) << 5) + r0]);
        const double h2d1 = (double)(h2p[((2 * g) << 5) + r1] + h2p[((2 * g + 1) << 5) + r1]);
        const size_t row0 = ((size_t)((g * Bdim + bidx) * Sdim) + sbase + r0) * (size_t)Vdim;
        const size_t row1 = ((size_t)((g * Bdim + bidx) * Sdim) + sbase + r1) * (size_t)Vdim;

        double m0 = 1e300, m1 = 1e300;
        int    i0 = 0,     i1 = 0;
#pragma unroll
        for (int j = 0; j < 10; j++) {
            int v0 = ((wn * 10 + j) << 3) + lq2;
            double2 cc = *(double2*)&c2d[g * Vdim + v0];
            double d00 = fma(-2.0, (double)acc2[j][0], cc.x);
            double d01 = fma(-2.0, (double)acc2[j][1], cc.y);
            double d10 = fma(-2.0, (double)acc2[j][2], cc.x);
            double d11 = fma(-2.0, (double)acc2[j][3], cc.y);
            *(float2*)(out + DIST_OFF + row0 + v0) =
                make_float2((float)(h2d0 + d00), (float)(h2d0 + d01));
            *(float2*)(out + DIST_OFF + row1 + v0) =
                make_float2((float)(h2d1 + d10), (float)(h2d1 + d11));
            if (d00 < m0) { m0 = d00; i0 = v0; }
            if (d01 < m0) { m0 = d01; i0 = v0 + 1; }
            if (d10 < m1) { m1 = d10; i1 = v0; }
            if (d11 < m1) { m1 = d11; i1 = v0 + 1; }
        }
        // reduce across the 4 lanes sharing each row
#pragma unroll
        for (int off = 1; off <= 2; off <<= 1) {
            double om = __shfl_xor_sync(0xffffffffu, m0, off);
            int    oi = __shfl_xor_sync(0xffffffffu, i0, off);
            if (om < m0 || (om == m0 && oi < i0)) { m0 = om; i0 = oi; }
            om = __shfl_xor_sync(0xffffffffu, m1, off);
            oi = __shfl_xor_sync(0xffffffffu, i1, off);
            if (om < m1 || (om == m1 && oi < i1)) { m1 = om; i1 = oi; }
        }
        if ((lane & 3) == 0) {
            amv[(r0 << 2) + wn] = m0; ami[(r0 << 2) + wn] = i0;
            amv[(r1 << 2) + wn] = m1; ami[(r1 << 2) + wn] = i1;
        }
        __syncthreads();
        if (tx < 32) {
            double bm = amv[tx << 2]; int bi = ami[tx << 2];
#pragma unroll
            for (int q = 1; q < 4; q++) {
                double om = amv[(tx << 2) + q]; int oi = ami[(tx << 2) + q];
                if (om < bm || (om == bm && oi < bi)) { bm = om; bi = oi; }
            }
            fmi[tx] = bi;
            atomicAdd(&g_counts[g * Vdim + bi], 1);
        }
        __syncthreads();
        const int mi0 = fmi[r0], mi1 = fmi[r1];
#pragma unroll
        for (int j = 0; j < 10; j++) {
            int v0 = ((wn * 10 + j) << 3) + lq2;
            *(float2*)(out + ENC_OFF + row0 + v0) =
                make_float2(v0 == mi0 ? 1.f : 0.f, v0 + 1 == mi0 ? 1.f : 0.f);
            *(float2*)(out + ENC_OFF + row1 + v0) =
                make_float2(v0 == mi1 ? 1.f : 0.f, v0 + 1 == mi1 ? 1.f : 0.f);
        }
        // quantized features: 8 threads per token gather 128 floats
        {
            int task = tx >> 3, l8 = tx & 7;
            int mi = fmi[task];
            const float4* cs = (const float4*)(C + ((size_t)(g * Vdim + mi)) * Ddim + (l8 << 4));
            float4* qd = (float4*)(out + Q_OFF + (size_t)(t0 + task) * GDdim + g * Ddim + (l8 << 4));
            qd[0] = cs[0]; qd[1] = cs[1]; qd[2] = cs[2]; qd[3] = cs[3];
        }
        __syncthreads();   // protect fmi/amv before next group's reuse
    }
}

// ---------------------------------------------------------------------------
// Perplexity: deterministic reduction
// ---------------------------------------------------------------------------
__global__ void perp_kernel(float* __restrict__ out) {
    __shared__ float ent[Gdim * Vdim];
    __shared__ float ex[Gdim];
    int i = threadIdx.x;
    if (i < Gdim * Vdim) {
        float p = (float)g_counts[i] * (1.0f / (float)NTOK);
        p = fminf(fmaxf(p, 1e-10f), 1.0f);
        ent[i] = p * logf(p + 1e-10f);
    }
    __syncthreads();
    if (i < Gdim) {
        float s = 0.f;
        for (int v = 0; v < Vdim; v++) s += ent[i * Vdim + v];
        ex[i] = expf(-s);
    }
    __syncthreads();
    if (i == 0) out[PERP_OFF] = 0.5f * (ex[0] + ex[1]);
}

// ---------------------------------------------------------------------------
extern "C" void kernel_launch(void* const* d_in, const int* in_sizes, int n_in,
                              void* d_out, int out_size) {
    const float* X    = (const float*)d_in[0];  // hidden_states [16,4096,512]
    const float* W    = (const float*)d_in[1];  // W_proj [512,256]
    const float* bias = (const float*)d_in[2];  // b_proj [256]
    const float* C    = (const float*)d_in[3];  // codevectors [2,320,128]
    float* out = (float*)d_out;

    cudaFuncSetAttribute(main_kernel, cudaFuncAttributeMaxDynamicSharedMemorySize,
                         SM_FLOATS * sizeof(float));

    prep_kernel<<<256, 256>>>(W, C);
    main_kernel<<<NCTA, 256, SM_FLOATS * sizeof(float)>>>(X, bias, C, out);
    perp_kernel<<<1, Gdim * Vdim>>>(out);
}

// round 5
// speedup vs baseline: 1.8999x; 1.1213x over previous
#include <cuda_runtime.h>

// Problem dims (fixed by the dataset)
#define Bdim 16
#define Sdim 4096
#define Hdim 512
#define Gdim 2
#define Vdim 320
#define Ddim 128
#define GDdim 256
#define NTOK (Bdim * Sdim)           // 65536
#define TOK 32
#define NCTA (NTOK / TOK)            // 2048

// Output layout (concatenated reference returns)
#define Q_OFF    0
#define ENC_OFF  16777216
#define DIST_OFF 58720256
#define PERP_OFF 100663296

#define TAU 0.0625f

// device scratch
__device__ float  g_WpH[Hdim * GDdim];       // W hi split, fragment-paired
__device__ float  g_WpL[Hdim * GDdim];       // W lo split, fragment-paired
__device__ float  g_Cp[Gdim * Vdim * Ddim];  // codevectors rna-tf32, fragment-paired
__device__ double g_c2d[Gdim * Vdim];        // exact ||c||^2
__device__ int    g_counts[Gdim * Vdim];

__device__ __forceinline__ void split2(float x, unsigned& hi, unsigned& lo) {
    unsigned xb = __float_as_uint(x);
    hi = xb & 0xFFFFE000u;
    lo = __float_as_uint(x - __uint_as_float(hi));
}

__device__ __forceinline__ void mma_tf32(float* c, const unsigned* a, const unsigned* b) {
    asm volatile(
        "mma.sync.aligned.m16n8k8.row.col.f32.tf32.tf32.f32 "
        "{%0,%1,%2,%3}, {%4,%5,%6,%7}, {%8,%9}, {%0,%1,%2,%3};\n"
        : "+f"(c[0]), "+f"(c[1]), "+f"(c[2]), "+f"(c[3])
        : "r"(a[0]), "r"(a[1]), "r"(a[2]), "r"(a[3]), "r"(b[0]), "r"(b[1]));
}

// ---------------------------------------------------------------------------
// Prep: counts=0, exact c2, W pre-split hi/lo into paired layout (16-k chunks),
// C rna-rounded into paired layout.
// ---------------------------------------------------------------------------
__global__ void prep_kernel(const float* __restrict__ W, const float* __restrict__ C) {
    int tid = blockIdx.x * blockDim.x + threadIdx.x;  // 65536 threads
    // W paired by 16-k chunk: off = (kc<<12) + (((kk<<5)+s)<<6) + 2l + slot
    for (int e = tid; e < Hdim * GDdim; e += 65536) {
        int k = e >> 8, n = e & 255;
        int kc = k >> 4, k16 = k & 15, kk = k16 >> 3, k8 = k16 & 7;
        int s = n >> 3, l = (k8 & 3) + ((n & 7) << 2), slot = k8 >> 2;
        int off = (kc << 12) + (((kk << 5) + s) << 6) + 2 * l + slot;
        float v = W[e];
        unsigned hb = __float_as_uint(v) & 0xFFFFE000u;
        float hi = __uint_as_float(hb);
        g_WpH[off] = hi;
        g_WpL[off] = v - hi;
    }
    // C paired: [g][kc=0..15][s=0..39][64], values rna-rounded to tf32
    for (int e = tid; e < Gdim * Vdim * Ddim; e += 65536) {
        int g = e / (Vdim * Ddim);
        int rem = e - g * (Vdim * Ddim);
        int v = rem >> 7, d = rem & 127;
        int kc = d >> 3, k8 = d & 7;
        int s = v >> 3, l = (k8 & 3) + ((v & 7) << 2), slot = k8 >> 2;
        unsigned r;
        asm("cvt.rna.tf32.f32 %0, %1;" : "=r"(r) : "f"(C[e]));
        g_Cp[(((g << 4) + kc) * 40 + s) * 64 + 2 * l + slot] = __uint_as_float(r);
    }
    // exact c2 (double): one warp per codevector
    int gw = tid >> 5, lane = tid & 31;
    if (gw < Gdim * Vdim) {
        float4 cv = *(const float4*)(C + (size_t)gw * Ddim + (lane << 2));
        double s = 0.0;
        s = fma((double)cv.x, (double)cv.x, s);
        s = fma((double)cv.y, (double)cv.y, s);
        s = fma((double)cv.z, (double)cv.z, s);
        s = fma((double)cv.w, (double)cv.w, s);
#pragma unroll
        for (int off = 16; off >= 1; off >>= 1)
            s += __shfl_xor_sync(0xffffffffu, s, off);
        if (lane == 0) { g_c2d[gw] = s; g_counts[gw] = 0; }
    }
}

// ---------------------------------------------------------------------------
// smem layout (float slots)
// ---------------------------------------------------------------------------
#define SM_HSP   0       // 8192: h fragment-paired [g][kc16][row][8]
#define SM_BUF   8192    // 8192: stage1 Whi(4096)+Wlo(4096) / stage2 C chunk 5120
#define SM_XP    16384   // 512
#define SM_BIAS  16896   // 256
#define SM_C2D   17152   // 640 doubles = 1280 slots (8B aligned)
#define SM_C2F   18432   // 640
#define SM_H2P   19072   // 128
#define SM_AMV   19200   // 128
#define SM_FMV   19328   // 32
#define SM_FMI   19360   // 32 (ints)
#define SM_RCNT  19392   // 32 (ints)
#define SM_RVID  19424   // 384 (ints): 32 rows x 12 slots
#define SM_FLOATS 19808

extern __shared__ float smem[];

__global__ __launch_bounds__(256, 2)
void main_kernel(const float* __restrict__ X,   // [B*S, 512]
                 const float* __restrict__ bias,// [256]
                 const float* __restrict__ C,   // [2,320,128]
                 float* __restrict__ out)
{
    float*  hsp  = smem + SM_HSP;
    float*  buf  = smem + SM_BUF;
    float*  Xp   = smem + SM_XP;
    float*  bs   = smem + SM_BIAS;
    double* c2d  = (double*)(smem + SM_C2D);
    float*  c2f  = smem + SM_C2F;
    float*  h2p  = smem + SM_H2P;
    float*  amv  = smem + SM_AMV;
    float*  fmv  = smem + SM_FMV;
    int*    fmi  = (int*)(smem + SM_FMI);
    int*    rcnt = (int*)(smem + SM_RCNT);
    int*    rvid = (int*)(smem + SM_RVID);

    const int tx   = threadIdx.x;
    const int lane = tx & 31;
    const int w    = tx >> 5;
    const int wm   = w & 1;
    const int wn   = w >> 1;
    const int t0   = blockIdx.x * TOK;
    const int r0   = (wm << 4) + (lane >> 2);
    const int r1   = r0 + 8;
    const int lq2  = (lane & 3) << 1;

    // preload c2 (double + float) and bias
    c2d[tx]       = g_c2d[tx];
    c2d[tx + 256] = g_c2d[tx + 256];
    if (tx < 128) c2d[tx + 512] = g_c2d[tx + 512];
    c2f[tx]       = (float)g_c2d[tx];
    c2f[tx + 256] = (float)g_c2d[tx + 256];
    if (tx < 128) c2f[tx + 512] = (float)g_c2d[tx + 512];
    bs[tx] = bias[tx];

    // ============ Stage 1: h = X @ W + b  (tf32x3, W pre-split) =============
    float acc[8][4];
#pragma unroll
    for (int i = 0; i < 8; i++)
#pragma unroll
        for (int j = 0; j < 4; j++) acc[i][j] = 0.f;

    const int ltok = tx >> 3;      // 0..31
    const int lqx  = tx & 7;       // 0..7

    for (int kc = 0; kc < 32; kc++) {           // 16-k chunks
        __syncthreads();
        // X tile -> paired Xp[kk][row][8]
        {
            float2 xv = *(const float2*)(X + (size_t)(t0 + ltok) * Hdim + (kc << 4) + (lqx << 1));
            int k0 = lqx << 1;
            int kk = k0 >> 3, k8a = k0 & 7, k8b = (k0 + 1) & 7;
            Xp[(kk << 8) + (ltok << 3) + ((k8a & 3) << 1) + (k8a >> 2)] = xv.x;
            Xp[(kk << 8) + (ltok << 3) + ((k8b & 3) << 1) + (k8b >> 2)] = xv.y;
        }
        // W chunk hi+lo (pre-split, pre-paired): 2x4096 floats
        {
            const float4* sH = (const float4*)(g_WpH + (kc << 12));
            const float4* sL = (const float4*)(g_WpL + (kc << 12));
            float4* dH = (float4*)buf;
            float4* dL = (float4*)(buf + 4096);
#pragma unroll
            for (int q = 0; q < 4; q++) {
                dH[tx + (q << 8)] = sH[tx + (q << 8)];
                dL[tx + (q << 8)] = sL[tx + (q << 8)];
            }
        }
        __syncthreads();
#pragma unroll
        for (int kk = 0; kk < 2; kk++) {
            float2 pa = *(float2*)&Xp[(kk << 8) + (r0 << 3) + lq2];
            float2 pb = *(float2*)&Xp[(kk << 8) + (r1 << 3) + lq2];
            unsigned ah[4], al[4];
            split2(pa.x, ah[0], al[0]); split2(pb.x, ah[1], al[1]);
            split2(pa.y, ah[2], al[2]); split2(pb.y, ah[3], al[3]);
#pragma unroll
            for (int s8 = 0; s8 < 8; s8++) {
                int off = (((kk << 5) + (wn << 3) + s8) << 6) + (lane << 1);
                float2 whi = *(float2*)&buf[off];
                float2 wlo = *(float2*)&buf[4096 + off];
                unsigned bh[2] = {__float_as_uint(whi.x), __float_as_uint(whi.y)};
                unsigned bl[2] = {__float_as_uint(wlo.x), __float_as_uint(wlo.y)};
                mma_tf32(acc[s8], ah, bh);
                mma_tf32(acc[s8], ah, bl);
                mma_tf32(acc[s8], al, bh);
            }
        }
    }

    // stage-1 epilogue: +bias, h2 partials, store h fragment-paired
    {
        float h2a = 0.f, h2b = 0.f;
#pragma unroll
        for (int s8 = 0; s8 < 8; s8++) {
            int s   = (wn << 3) + s8;
            int col = (s << 3) + lq2;
            float2 bb = *(float2*)&bs[col];
            float v0 = acc[s8][0] + bb.x;
            float v1 = acc[s8][1] + bb.y;
            float v2 = acc[s8][2] + bb.x;
            float v3 = acc[s8][3] + bb.y;
            h2a = fmaf(v0, v0, h2a); h2a = fmaf(v1, v1, h2a);
            h2b = fmaf(v2, v2, h2b); h2b = fmaf(v3, v3, h2b);
            int g = col >> 7, cg = col & 127;
            int kc = cg >> 3, k8 = cg & 7;
            int p0 = k8 & 3, sl0 = k8 >> 2;
            int k8b = k8 + 1, p1 = k8b & 3, sl1 = k8b >> 2;
            int base = (((g << 4) + kc) << 5);
            hsp[((base + r0) << 3) + (p0 << 1) + sl0] = v0;
            hsp[((base + r0) << 3) + (p1 << 1) + sl1] = v1;
            hsp[((base + r1) << 3) + (p0 << 1) + sl0] = v2;
            hsp[((base + r1) << 3) + (p1 << 1) + sl1] = v3;
        }
        h2a += __shfl_xor_sync(0xffffffffu, h2a, 1);
        h2a += __shfl_xor_sync(0xffffffffu, h2a, 2);
        h2b += __shfl_xor_sync(0xffffffffu, h2b, 1);
        h2b += __shfl_xor_sync(0xffffffffu, h2b, 2);
        if ((lane & 3) == 0) {
            h2p[(wn << 5) + r0] = h2a;
            h2p[(wn << 5) + r1] = h2b;
        }
    }

    // ============ Stage 2: hc (tf32x1) + exact-rescue argmin ================
    const int bidx  = t0 >> 12;
    const int sbase = t0 & 4095;

    for (int g = 0; g < Gdim; g++) {
        float acc2[10][4];
#pragma unroll
        for (int i = 0; i < 10; i++)
#pragma unroll
            for (int j = 0; j < 4; j++) acc2[i][j] = 0.f;

        for (int kc2 = 0; kc2 < 8; kc2++) {
            __syncthreads();
            {
                const float4* src = (const float4*)(g_Cp + ((((g << 4) + (kc2 << 1)) * 40) << 6));
                float4* dst = (float4*)buf;
#pragma unroll
                for (int q = 0; q < 5; q++) dst[tx + (q << 8)] = src[tx + (q << 8)];
            }
            __syncthreads();
#pragma unroll
            for (int kk = 0; kk < 2; kk++) {
                int kcx = (kc2 << 1) + kk;
                int hb = (((g << 4) + kcx) << 5);
                float2 pa = *(float2*)&hsp[((hb + r0) << 3) + lq2];
                float2 pb = *(float2*)&hsp[((hb + r1) << 3) + lq2];
                unsigned a[4] = {__float_as_uint(pa.x), __float_as_uint(pb.x),
                                 __float_as_uint(pa.y), __float_as_uint(pb.y)};
#pragma unroll
                for (int j = 0; j < 10; j++) {
                    float2 pw = *(float2*)&buf[((kk * 40 + wn * 10 + j) << 6) + (lane << 1)];
                    unsigned b[2] = {__float_as_uint(pw.x), __float_as_uint(pw.y)};
                    mma_tf32(acc2[j], a, b);
                }
            }
        }

        // ---- epilogue: approx keys, distances out, approx min ----
        const float h2f0 = h2p[((2 * g) << 5) + r0] + h2p[((2 * g + 1) << 5) + r0];
        const float h2f1 = h2p[((2 * g) << 5) + r1] + h2p[((2 * g + 1) << 5) + r1];
        const size_t row0 = ((size_t)((g * Bdim + bidx) * Sdim) + sbase + r0) * (size_t)Vdim;
        const size_t row1 = ((size_t)((g * Bdim + bidx) * Sdim) + sbase + r1) * (size_t)Vdim;

        float m0 = 1e30f, m1 = 1e30f;
#pragma unroll
        for (int j = 0; j < 10; j++) {
            int v0 = ((wn * 10 + j) << 3) + lq2;
            float2 cc = *(float2*)&c2f[g * Vdim + v0];
            float k00 = fmaf(-2.f, acc2[j][0], cc.x);
            float k01 = fmaf(-2.f, acc2[j][1], cc.y);
            float k10 = fmaf(-2.f, acc2[j][2], cc.x);
            float k11 = fmaf(-2.f, acc2[j][3], cc.y);
            *(float2*)(out + DIST_OFF + row0 + v0) = make_float2(h2f0 + k00, h2f0 + k01);
            *(float2*)(out + DIST_OFF + row1 + v0) = make_float2(h2f1 + k10, h2f1 + k11);
            m0 = fminf(m0, fminf(k00, k01));
            m1 = fminf(m1, fminf(k10, k11));
        }
#pragma unroll
        for (int off = 1; off <= 2; off <<= 1) {
            m0 = fminf(m0, __shfl_xor_sync(0xffffffffu, m0, off));
            m1 = fminf(m1, __shfl_xor_sync(0xffffffffu, m1, off));
        }
        if ((lane & 3) == 0) {
            amv[(r0 << 2) + wn] = m0;
            amv[(r1 << 2) + wn] = m1;
        }
        __syncthreads();
        if (tx < 32) {
            float b = amv[tx << 2];
            b = fminf(b, amv[(tx << 2) + 1]);
            b = fminf(b, amv[(tx << 2) + 2]);
            b = fminf(b, amv[(tx << 2) + 3]);
            fmv[tx] = b;
            rcnt[tx] = 0;
        }
        __syncthreads();
        // flag candidates within TAU of approx min
        {
            float thr0 = fmv[r0] + TAU, thr1 = fmv[r1] + TAU;
#pragma unroll
            for (int j = 0; j < 10; j++) {
                int v0 = ((wn * 10 + j) << 3) + lq2;
                float2 cc = *(float2*)&c2f[g * Vdim + v0];
                float k00 = fmaf(-2.f, acc2[j][0], cc.x);
                float k01 = fmaf(-2.f, acc2[j][1], cc.y);
                float k10 = fmaf(-2.f, acc2[j][2], cc.x);
                float k11 = fmaf(-2.f, acc2[j][3], cc.y);
                if (k00 <= thr0) { int s = atomicAdd(&rcnt[r0], 1); if (s < 12) rvid[r0 * 12 + s] = v0; }
                if (k01 <= thr0) { int s = atomicAdd(&rcnt[r0], 1); if (s < 12) rvid[r0 * 12 + s] = v0 + 1; }
                if (k10 <= thr1) { int s = atomicAdd(&rcnt[r1], 1); if (s < 12) rvid[r1 * 12 + s] = v0; }
                if (k11 <= thr1) { int s = atomicAdd(&rcnt[r1], 1); if (s < 12) rvid[r1 * 12 + s] = v0 + 1; }
            }
        }
        __syncthreads();
        // exact rescue: warp w handles rows 4w..4w+3
        {
#pragma unroll
            for (int q = 0; q < 4; q++) {
                int r = (w << 2) + q;
                // this lane's 4 h dims for row r (exact fp32 h from smem)
                double hd[4];
#pragma unroll
                for (int e = 0; e < 4; e++) {
                    int d = (lane << 2) + e;
                    int kcq = d >> 3, k8 = d & 7;
                    hd[e] = (double)hsp[(((((g << 4) + kcq) << 5) + r) << 3) + ((k8 & 3) << 1) + (k8 >> 2)];
                }
                int n = rcnt[r]; if (n > 12) n = 12;
                double bk = 1e300; int bv = 0x7fffffff;
                for (int i = 0; i < n; i++) {
                    int v = rvid[r * 12 + i];
                    float4 cv = *(const float4*)(C + ((size_t)(g * Vdim + v)) * Ddim + (lane << 2));
                    double dot = 0.0;
                    dot = fma(hd[0], (double)cv.x, dot);
                    dot = fma(hd[1], (double)cv.y, dot);
                    dot = fma(hd[2], (double)cv.z, dot);
                    dot = fma(hd[3], (double)cv.w, dot);
#pragma unroll
                    for (int off = 16; off >= 1; off >>= 1)
                        dot += __shfl_xor_sync(0xffffffffu, dot, off);
                    double key = fma(-2.0, dot, c2d[g * Vdim + v]);
                    if (key < bk || (key == bk && v < bv)) { bk = key; bv = v; }
                }
                if (lane == 0) {
                    fmi[r] = bv;
                    atomicAdd(&g_counts[g * Vdim + bv], 1);
                }
            }
        }
        __syncthreads();
        // encodings + quantized gather
        const int mi0 = fmi[r0], mi1 = fmi[r1];
#pragma unroll
        for (int j = 0; j < 10; j++) {
            int v0 = ((wn * 10 + j) << 3) + lq2;
            *(float2*)(out + ENC_OFF + row0 + v0) =
                make_float2(v0 == mi0 ? 1.f : 0.f, v0 + 1 == mi0 ? 1.f : 0.f);
            *(float2*)(out + ENC_OFF + row1 + v0) =
                make_float2(v0 == mi1 ? 1.f : 0.f, v0 + 1 == mi1 ? 1.f : 0.f);
        }
        {
            int task = tx >> 3, l8 = tx & 7;
            int mi = fmi[task];
            const float4* cs = (const float4*)(C + ((size_t)(g * Vdim + mi)) * Ddim + (l8 << 4));
            float4* qd = (float4*)(out + Q_OFF + (size_t)(t0 + task) * GDdim + g * Ddim + (l8 << 4));
            qd[0] = cs[0]; qd[1] = cs[1]; qd[2] = cs[2]; qd[3] = cs[3];
        }
        __syncthreads();
    }
}

// ---------------------------------------------------------------------------
__global__ void perp_kernel(float* __restrict__ out) {
    __shared__ float ent[Gdim * Vdim];
    __shared__ float ex[Gdim];
    int i = threadIdx.x;
    if (i < Gdim * Vdim) {
        float p = (float)g_counts[i] * (1.0f / (float)NTOK);
        p = fminf(fmaxf(p, 1e-10f), 1.0f);
        ent[i] = p * logf(p + 1e-10f);
    }
    __syncthreads();
    if (i < Gdim) {
        float s = 0.f;
        for (int v = 0; v < Vdim; v++) s += ent[i * Vdim + v];
        ex[i] = expf(-s);
    }
    __syncthreads();
    if (i == 0) out[PERP_OFF] = 0.5f * (ex[0] + ex[1]);
}

// ---------------------------------------------------------------------------
extern "C" void kernel_launch(void* const* d_in, const int* in_sizes, int n_in,
                              void* d_out, int out_size) {
    const float* X    = (const float*)d_in[0];
    const float* W    = (const float*)d_in[1];
    const float* bias = (const float*)d_in[2];
    const float* C    = (const float*)d_in[3];
    float* out = (float*)d_out;

    cudaFuncSetAttribute(main_kernel, cudaFuncAttributeMaxDynamicSharedMemorySize,
                         SM_FLOATS * sizeof(float));

    prep_kernel<<<256, 256>>>(W, C);
    main_kernel<<<NCTA, 256, SM_FLOATS * sizeof(float)>>>(X, bias, C, out);
    perp_kernel<<<1, Gdim * Vdim>>>(out);
}

// round 6
// speedup vs baseline: 2.3180x; 1.2201x over previous
#include <cuda_runtime.h>

// Problem dims (fixed by the dataset)
#define Bdim 16
#define Sdim 4096
#define Hdim 512
#define Gdim 2
#define Vdim 320
#define Ddim 128
#define GDdim 256
#define NTOK (Bdim * Sdim)           // 65536
#define TOK 32
#define NCTA (NTOK / TOK)            // 2048

// Output layout (concatenated reference returns)
#define Q_OFF    0
#define ENC_OFF  16777216
#define DIST_OFF 58720256
#define PERP_OFF 100663296

#define TAU 0.0625f

// device scratch
__device__ float  g_WpH[Hdim * GDdim];       // W hi split, fragment-paired
__device__ float  g_WpL[Hdim * GDdim];       // W lo split, fragment-paired
__device__ float  g_Cp[Gdim * Vdim * Ddim];  // codevectors rna-tf32, fragment-paired
__device__ double g_c2d[Gdim * Vdim];        // exact ||c||^2
__device__ int    g_counts[Gdim * Vdim];

__device__ __forceinline__ void split2(float x, unsigned& hi, unsigned& lo) {
    unsigned xb = __float_as_uint(x);
    hi = xb & 0xFFFFE000u;
    lo = __float_as_uint(x - __uint_as_float(hi));
}

__device__ __forceinline__ void mma_tf32(float* c, const unsigned* a, const unsigned* b) {
    asm volatile(
        "mma.sync.aligned.m16n8k8.row.col.f32.tf32.tf32.f32 "
        "{%0,%1,%2,%3}, {%4,%5,%6,%7}, {%8,%9}, {%0,%1,%2,%3};\n"
        : "+f"(c[0]), "+f"(c[1]), "+f"(c[2]), "+f"(c[3])
        : "r"(a[0]), "r"(a[1]), "r"(a[2]), "r"(a[3]), "r"(b[0]), "r"(b[1]));
}

__device__ __forceinline__ void cpa16(float* s, const float* g) {
    unsigned sa = (unsigned)__cvta_generic_to_shared(s);
    asm volatile("cp.async.cg.shared.global [%0], [%1], 16;\n" :: "r"(sa), "l"(g));
}
#define CPA_COMMIT() asm volatile("cp.async.commit_group;\n" ::: "memory")
#define CPA_WAIT0()  asm volatile("cp.async.wait_group 0;\n" ::: "memory")

// ---------------------------------------------------------------------------
// Prep: counts=0, exact c2, W pre-split hi/lo paired (16-k chunks), C paired.
// ---------------------------------------------------------------------------
__global__ void prep_kernel(const float* __restrict__ W, const float* __restrict__ C) {
    int tid = blockIdx.x * blockDim.x + threadIdx.x;  // 65536 threads
    for (int e = tid; e < Hdim * GDdim; e += 65536) {
        int k = e >> 8, n = e & 255;
        int kc = k >> 4, k16 = k & 15, kk = k16 >> 3, k8 = k16 & 7;
        int s = n >> 3, l = (k8 & 3) + ((n & 7) << 2), slot = k8 >> 2;
        int off = (kc << 12) + (((kk << 5) + s) << 6) + 2 * l + slot;
        float v = W[e];
        unsigned hb = __float_as_uint(v) & 0xFFFFE000u;
        float hi = __uint_as_float(hb);
        g_WpH[off] = hi;
        g_WpL[off] = v - hi;
    }
    for (int e = tid; e < Gdim * Vdim * Ddim; e += 65536) {
        int g = e / (Vdim * Ddim);
        int rem = e - g * (Vdim * Ddim);
        int v = rem >> 7, d = rem & 127;
        int kc = d >> 3, k8 = d & 7;
        int s = v >> 3, l = (k8 & 3) + ((v & 7) << 2), slot = k8 >> 2;
        unsigned r;
        asm("cvt.rna.tf32.f32 %0, %1;" : "=r"(r) : "f"(C[e]));
        g_Cp[(((g << 4) + kc) * 40 + s) * 64 + 2 * l + slot] = __uint_as_float(r);
    }
    int gw = tid >> 5, lane = tid & 31;
    if (gw < Gdim * Vdim) {
        float4 cv = *(const float4*)(C + (size_t)gw * Ddim + (lane << 2));
        double s = 0.0;
        s = fma((double)cv.x, (double)cv.x, s);
        s = fma((double)cv.y, (double)cv.y, s);
        s = fma((double)cv.z, (double)cv.z, s);
        s = fma((double)cv.w, (double)cv.w, s);
#pragma unroll
        for (int off = 16; off >= 1; off >>= 1)
            s += __shfl_xor_sync(0xffffffffu, s, off);
        if (lane == 0) { g_c2d[gw] = s; g_counts[gw] = 0; }
    }
}

// ---------------------------------------------------------------------------
// smem layout (float slots)
// ---------------------------------------------------------------------------
#define SM_HSP   0       // 8192
#define SM_BUF   8192    // 16384: double-buffered W (2x8192) / C (2x5120)
#define SM_XP    24576   // 1024: double-buffered X paired (2x512)
#define SM_BIAS  25600   // 256
#define SM_C2F   25856   // 640
#define SM_H2P   26496   // 128
#define SM_AMV   26624   // 128
#define SM_FMV   26752   // 32
#define SM_FMI   26784   // 32 (ints)
#define SM_RCNT  26816   // 32 (ints)
#define SM_RVID  26848   // 384 (ints)
#define SM_FLOATS 27232  // ~106.4 KB

extern __shared__ float smem[];

__global__ __launch_bounds__(256, 2)
void main_kernel(const float* __restrict__ X,   // [B*S, 512]
                 const float* __restrict__ bias,// [256]
                 const float* __restrict__ C,   // [2,320,128]
                 float* __restrict__ out)
{
    float*  hsp  = smem + SM_HSP;
    float*  buf  = smem + SM_BUF;
    float*  Xp   = smem + SM_XP;
    float*  bs   = smem + SM_BIAS;
    float*  c2f  = smem + SM_C2F;
    float*  h2p  = smem + SM_H2P;
    float*  amv  = smem + SM_AMV;
    float*  fmv  = smem + SM_FMV;
    int*    fmi  = (int*)(smem + SM_FMI);
    int*    rcnt = (int*)(smem + SM_RCNT);
    int*    rvid = (int*)(smem + SM_RVID);

    const int tx   = threadIdx.x;
    const int lane = tx & 31;
    const int w    = tx >> 5;
    const int wm   = w & 1;
    const int wn   = w >> 1;
    const int t0   = blockIdx.x * TOK;
    const int r0   = (wm << 4) + (lane >> 2);
    const int r1   = r0 + 8;
    const int lq2  = (lane & 3) << 1;

    const int ltok = tx >> 3;      // 0..31
    const int lqx  = tx & 7;       // 0..7
    const int xk0  = lqx << 1;
    const int xkk  = xk0 >> 3;
    const int xk8a = xk0 & 7, xk8b = (xk0 + 1) & 7;
    const int xpo0 = (xkk << 8) + (ltok << 3) + ((xk8a & 3) << 1) + (xk8a >> 2);
    const int xpo1 = (xkk << 8) + (ltok << 3) + ((xk8b & 3) << 1) + (xk8b >> 2);
    const float* xrow = X + (size_t)(t0 + ltok) * Hdim + xk0;

    // preload c2f and bias (covered by first __syncthreads)
    c2f[tx]       = (float)g_c2d[tx];
    c2f[tx + 256] = (float)g_c2d[tx + 256];
    if (tx < 128) c2f[tx + 512] = (float)g_c2d[tx + 512];
    bs[tx] = bias[tx];

    // ============ Stage 1: h = X @ W + b  (tf32x3, pipelined) ===============
    float acc[8][4];
#pragma unroll
    for (int i = 0; i < 8; i++)
#pragma unroll
        for (int j = 0; j < 4; j++) acc[i][j] = 0.f;

    // preload chunk 0
    {
        float2 xv = *(const float2*)(xrow);
        Xp[xpo0] = xv.x; Xp[xpo1] = xv.y;
        const float* sH = g_WpH;
        const float* sL = g_WpL;
#pragma unroll
        for (int q = 0; q < 4; q++) {
            cpa16(buf + ((tx + (q << 8)) << 2), sH + ((tx + (q << 8)) << 2));
            cpa16(buf + 4096 + ((tx + (q << 8)) << 2), sL + ((tx + (q << 8)) << 2));
        }
        CPA_COMMIT();
    }
    CPA_WAIT0();
    __syncthreads();

    for (int kc = 0; kc < 32; kc++) {
        const int cur = kc & 1, nxt = cur ^ 1;
        if (kc < 31) {
            // prefetch X(kc+1) via registers (store into alternate Xp half)
            float2 xv = *(const float2*)(xrow + ((kc + 1) << 4));
            Xp[nxt * 512 + xpo0] = xv.x;
            Xp[nxt * 512 + xpo1] = xv.y;
            // prefetch W(kc+1) via cp.async into alternate buffer
            const float* sH = g_WpH + ((kc + 1) << 12);
            const float* sL = g_WpL + ((kc + 1) << 12);
            float* dH = buf + nxt * 8192;
            float* dL = buf + nxt * 8192 + 4096;
#pragma unroll
            for (int q = 0; q < 4; q++) {
                cpa16(dH + ((tx + (q << 8)) << 2), sH + ((tx + (q << 8)) << 2));
                cpa16(dL + ((tx + (q << 8)) << 2), sL + ((tx + (q << 8)) << 2));
            }
            CPA_COMMIT();
        }
        // MMAs on current chunk
        const float* bw = buf + cur * 8192;
        const float* xp = Xp + cur * 512;
#pragma unroll
        for (int kk = 0; kk < 2; kk++) {
            float2 pa = *(float2*)&xp[(kk << 8) + (r0 << 3) + lq2];
            float2 pb = *(float2*)&xp[(kk << 8) + (r1 << 3) + lq2];
            unsigned ah[4], al[4];
            split2(pa.x, ah[0], al[0]); split2(pb.x, ah[1], al[1]);
            split2(pa.y, ah[2], al[2]); split2(pb.y, ah[3], al[3]);
#pragma unroll
            for (int s8 = 0; s8 < 8; s8++) {
                int off = (((kk << 5) + (wn << 3) + s8) << 6) + (lane << 1);
                float2 whi = *(float2*)&bw[off];
                float2 wlo = *(float2*)&bw[4096 + off];
                unsigned bh[2] = {__float_as_uint(whi.x), __float_as_uint(whi.y)};
                unsigned bl[2] = {__float_as_uint(wlo.x), __float_as_uint(wlo.y)};
                mma_tf32(acc[s8], ah, bh);
                mma_tf32(acc[s8], ah, bl);
                mma_tf32(acc[s8], al, bh);
            }
        }
        CPA_WAIT0();
        __syncthreads();
    }

    // prefetch stage-2 group-0 chunk-0 into bufC[0] (= buf[0:5120); last W
    // buffer was buf[8192:16384) -> no overlap)
    {
        const float* src = g_Cp;
#pragma unroll
        for (int q = 0; q < 5; q++)
            cpa16(buf + ((tx + (q << 8)) << 2), src + ((tx + (q << 8)) << 2));
        CPA_COMMIT();
    }

    // stage-1 epilogue: +bias, h2 partials, store h fragment-paired
    {
        float h2a = 0.f, h2b = 0.f;
#pragma unroll
        for (int s8 = 0; s8 < 8; s8++) {
            int s   = (wn << 3) + s8;
            int col = (s << 3) + lq2;
            float2 bb = *(float2*)&bs[col];
            float v0 = acc[s8][0] + bb.x;
            float v1 = acc[s8][1] + bb.y;
            float v2 = acc[s8][2] + bb.x;
            float v3 = acc[s8][3] + bb.y;
            h2a = fmaf(v0, v0, h2a); h2a = fmaf(v1, v1, h2a);
            h2b = fmaf(v2, v2, h2b); h2b = fmaf(v3, v3, h2b);
            int g = col >> 7, cg = col & 127;
            int kc = cg >> 3, k8 = cg & 7;
            int p0 = k8 & 3, sl0 = k8 >> 2;
            int k8b = k8 + 1, p1 = k8b & 3, sl1 = k8b >> 2;
            int base = (((g << 4) + kc) << 5);
            hsp[((base + r0) << 3) + (p0 << 1) + sl0] = v0;
            hsp[((base + r0) << 3) + (p1 << 1) + sl1] = v1;
            hsp[((base + r1) << 3) + (p0 << 1) + sl0] = v2;
            hsp[((base + r1) << 3) + (p1 << 1) + sl1] = v3;
        }
        h2a += __shfl_xor_sync(0xffffffffu, h2a, 1);
        h2a += __shfl_xor_sync(0xffffffffu, h2a, 2);
        h2b += __shfl_xor_sync(0xffffffffu, h2b, 1);
        h2b += __shfl_xor_sync(0xffffffffu, h2b, 2);
        if ((lane & 3) == 0) {
            h2p[(wn << 5) + r0] = h2a;
            h2p[(wn << 5) + r1] = h2b;
        }
    }
    CPA_WAIT0();
    __syncthreads();

    // ============ Stage 2: hc (tf32x1, pipelined) + exact-rescue argmin =====
    const int bidx  = t0 >> 12;
    const int sbase = t0 & 4095;

    for (int g = 0; g < Gdim; g++) {
        float acc2[10][4];
#pragma unroll
        for (int i = 0; i < 10; i++)
#pragma unroll
            for (int j = 0; j < 4; j++) acc2[i][j] = 0.f;

        for (int kc2 = 0; kc2 < 8; kc2++) {
            const int cur = kc2 & 1, nxt = cur ^ 1;
            // prefetch next chunk (or next group's first chunk)
            if (kc2 < 7) {
                const float* src = g_Cp + ((g << 4) + ((kc2 + 1) << 1)) * 2560;
                float* dst = buf + nxt * 5120;
#pragma unroll
                for (int q = 0; q < 5; q++)
                    cpa16(dst + ((tx + (q << 8)) << 2), src + ((tx + (q << 8)) << 2));
                CPA_COMMIT();
            } else if (g == 0) {
                const float* src = g_Cp + 16 * 2560;   // g=1, chunk 0
                float* dst = buf + nxt * 5120;
#pragma unroll
                for (int q = 0; q < 5; q++)
                    cpa16(dst + ((tx + (q << 8)) << 2), src + ((tx + (q << 8)) << 2));
                CPA_COMMIT();
            }
            const float* bc = buf + cur * 5120;
#pragma unroll
            for (int kk = 0; kk < 2; kk++) {
                int kcx = (kc2 << 1) + kk;
                int hb = (((g << 4) + kcx) << 5);
                float2 pa = *(float2*)&hsp[((hb + r0) << 3) + lq2];
                float2 pb = *(float2*)&hsp[((hb + r1) << 3) + lq2];
                unsigned a[4] = {__float_as_uint(pa.x), __float_as_uint(pb.x),
                                 __float_as_uint(pa.y), __float_as_uint(pb.y)};
#pragma unroll
                for (int j = 0; j < 10; j++) {
                    float2 pw = *(float2*)&bc[((kk * 40 + wn * 10 + j) << 6) + (lane << 1)];
                    unsigned b[2] = {__float_as_uint(pw.x), __float_as_uint(pw.y)};
                    mma_tf32(acc2[j], a, b);
                }
            }
            CPA_WAIT0();
            __syncthreads();
        }

        // ---- epilogue: approx keys, distances out, approx min ----
        const float h2f0 = h2p[((2 * g) << 5) + r0] + h2p[((2 * g + 1) << 5) + r0];
        const float h2f1 = h2p[((2 * g) << 5) + r1] + h2p[((2 * g + 1) << 5) + r1];
        const size_t row0 = ((size_t)((g * Bdim + bidx) * Sdim) + sbase + r0) * (size_t)Vdim;
        const size_t row1 = ((size_t)((g * Bdim + bidx) * Sdim) + sbase + r1) * (size_t)Vdim;

        float m0 = 1e30f, m1 = 1e30f;
#pragma unroll
        for (int j = 0; j < 10; j++) {
            int v0 = ((wn * 10 + j) << 3) + lq2;
            float2 cc = *(float2*)&c2f[g * Vdim + v0];
            float k00 = fmaf(-2.f, acc2[j][0], cc.x);
            float k01 = fmaf(-2.f, acc2[j][1], cc.y);
            float k10 = fmaf(-2.f, acc2[j][2], cc.x);
            float k11 = fmaf(-2.f, acc2[j][3], cc.y);
            *(float2*)(out + DIST_OFF + row0 + v0) = make_float2(h2f0 + k00, h2f0 + k01);
            *(float2*)(out + DIST_OFF + row1 + v0) = make_float2(h2f1 + k10, h2f1 + k11);
            m0 = fminf(m0, fminf(k00, k01));
            m1 = fminf(m1, fminf(k10, k11));
        }
#pragma unroll
        for (int off = 1; off <= 2; off <<= 1) {
            m0 = fminf(m0, __shfl_xor_sync(0xffffffffu, m0, off));
            m1 = fminf(m1, __shfl_xor_sync(0xffffffffu, m1, off));
        }
        if ((lane & 3) == 0) {
            amv[(r0 << 2) + wn] = m0;
            amv[(r1 << 2) + wn] = m1;
        }
        __syncthreads();
        if (tx < 32) {
            float b = amv[tx << 2];
            b = fminf(b, amv[(tx << 2) + 1]);
            b = fminf(b, amv[(tx << 2) + 2]);
            b = fminf(b, amv[(tx << 2) + 3]);
            fmv[tx] = b;
            rcnt[tx] = 0;
        }
        __syncthreads();
        // flag candidates within TAU of approx min
        {
            float thr0 = fmv[r0] + TAU, thr1 = fmv[r1] + TAU;
#pragma unroll
            for (int j = 0; j < 10; j++) {
                int v0 = ((wn * 10 + j) << 3) + lq2;
                float2 cc = *(float2*)&c2f[g * Vdim + v0];
                float k00 = fmaf(-2.f, acc2[j][0], cc.x);
                float k01 = fmaf(-2.f, acc2[j][1], cc.y);
                float k10 = fmaf(-2.f, acc2[j][2], cc.x);
                float k11 = fmaf(-2.f, acc2[j][3], cc.y);
                if (k00 <= thr0) { int s = atomicAdd(&rcnt[r0], 1); if (s < 12) rvid[r0 * 12 + s] = v0; }
                if (k01 <= thr0) { int s = atomicAdd(&rcnt[r0], 1); if (s < 12) rvid[r0 * 12 + s] = v0 + 1; }
                if (k10 <= thr1) { int s = atomicAdd(&rcnt[r1], 1); if (s < 12) rvid[r1 * 12 + s] = v0; }
                if (k11 <= thr1) { int s = atomicAdd(&rcnt[r1], 1); if (s < 12) rvid[r1 * 12 + s] = v0 + 1; }
            }
        }
        __syncthreads();
        // exact rescue: warp w handles rows 4w..4w+3
        {
#pragma unroll
            for (int q = 0; q < 4; q++) {
                int r = (w << 2) + q;
                double hd[4];
#pragma unroll
                for (int e = 0; e < 4; e++) {
                    int d = (lane << 2) + e;
                    int kcq = d >> 3, k8 = d & 7;
                    hd[e] = (double)hsp[(((((g << 4) + kcq) << 5) + r) << 3) + ((k8 & 3) << 1) + (k8 >> 2)];
                }
                int n = rcnt[r]; if (n > 12) n = 12;
                double bk = 1e300; int bv = 0x7fffffff;
                for (int i = 0; i < n; i++) {
                    int v = rvid[r * 12 + i];
                    float4 cv = *(const float4*)(C + ((size_t)(g * Vdim + v)) * Ddim + (lane << 2));
                    double dot = 0.0;
                    dot = fma(hd[0], (double)cv.x, dot);
                    dot = fma(hd[1], (double)cv.y, dot);
                    dot = fma(hd[2], (double)cv.z, dot);
                    dot = fma(hd[3], (double)cv.w, dot);
#pragma unroll
                    for (int off = 16; off >= 1; off >>= 1)
                        dot += __shfl_xor_sync(0xffffffffu, dot, off);
                    double key = fma(-2.0, dot, g_c2d[g * Vdim + v]);
                    if (key < bk || (key == bk && v < bv)) { bk = key; bv = v; }
                }
                if (lane == 0) {
                    fmi[r] = bv;
                    atomicAdd(&g_counts[g * Vdim + bv], 1);
                }
            }
        }
        __syncthreads();
        // encodings + quantized gather
        const int mi0 = fmi[r0], mi1 = fmi[r1];
#pragma unroll
        for (int j = 0; j < 10; j++) {
            int v0 = ((wn * 10 + j) << 3) + lq2;
            *(float2*)(out + ENC_OFF + row0 + v0) =
                make_float2(v0 == mi0 ? 1.f : 0.f, v0 + 1 == mi0 ? 1.f : 0.f);
            *(float2*)(out + ENC_OFF + row1 + v0) =
                make_float2(v0 == mi1 ? 1.f : 0.f, v0 + 1 == mi1 ? 1.f : 0.f);
        }
        {
            int task = tx >> 3, l8 = tx & 7;
            int mi = fmi[task];
            const float4* cs = (const float4*)(C + ((size_t)(g * Vdim + mi)) * Ddim + (l8 << 4));
            float4* qd = (float4*)(out + Q_OFF + (size_t)(t0 + task) * GDdim + g * Ddim + (l8 << 4));
            qd[0] = cs[0]; qd[1] = cs[1]; qd[2] = cs[2]; qd[3] = cs[3];
        }
        __syncthreads();
    }
}

// ---------------------------------------------------------------------------
__global__ void perp_kernel(float* __restrict__ out) {
    __shared__ float ent[Gdim * Vdim];
    __shared__ float ex[Gdim];
    int i = threadIdx.x;
    if (i < Gdim * Vdim) {
        float p = (float)g_counts[i] * (1.0f / (float)NTOK);
        p = fminf(fmaxf(p, 1e-10f), 1.0f);
        ent[i] = p * logf(p + 1e-10f);
    }
    __syncthreads();
    if (i < Gdim) {
        float s = 0.f;
        for (int v = 0; v < Vdim; v++) s += ent[i * Vdim + v];
        ex[i] = expf(-s);
    }
    __syncthreads();
    if (i == 0) out[PERP_OFF] = 0.5f * (ex[0] + ex[1]);
}

// ---------------------------------------------------------------------------
extern "C" void kernel_launch(void* const* d_in, const int* in_sizes, int n_in,
                              void* d_out, int out_size) {
    const float* X    = (const float*)d_in[0];
    const float* W    = (const float*)d_in[1];
    const float* bias = (const float*)d_in[2];
    const float* C    = (const float*)d_in[3];
    float* out = (float*)d_out;

    cudaFuncSetAttribute(main_kernel, cudaFuncAttributeMaxDynamicSharedMemorySize,
                         SM_FLOATS * sizeof(float));

    prep_kernel<<<256, 256>>>(W, C);
    main_kernel<<<NCTA, 256, SM_FLOATS * sizeof(float)>>>(X, bias, C, out);
    perp_kernel<<<1, Gdim * Vdim>>>(out);
}